// round 6
// baseline (speedup 1.0000x reference)
#include <cuda_runtime.h>
#include <cuda_bf16.h>
#include <cstdint>

// Problem constants
#define BT 16          // b*t
#define C_ 64          // dim
#define HID 128
#define P 16384        // H*W = 128*128
typedef __nv_bfloat16 bf16;

// ---------------- scratch (device globals; no runtime allocation) ------------
__device__ bf16  g_xnb[(size_t)BT * P * C_];     // layernormed x, bf16 [bt][p][c]
__device__ bf16  g_x1[(size_t)BT * HID * P];     // pin out ch 0..127, bf16 [bt][ch][p]
__device__ bf16  g_x2[(size_t)BT * HID * P];     // pin out ch 128..255
__device__ bf16  g_gated[(size_t)BT * HID * P];  // (dyn dwconv + bias) * x2, [bt][ch][p]
__device__ float g_pooled[BT * HID];
__device__ float g_kern[BT * HID * 9];
__device__ bf16  g_pinTb[3 * 256 * 64];          // [dt][n(256)][c(64)]
__device__ bf16  g_poutTb[3 * 64 * 128];         // [dt][n(64)][k(128)]

// ---------------- helpers -----------------------------------------------------
__device__ __forceinline__ uint32_t smem_u32(const void* p) {
    return (uint32_t)__cvta_generic_to_shared(p);
}
__device__ __forceinline__ void cp16(uint32_t d, const void* s) {
    asm volatile("cp.async.cg.shared.global [%0], [%1], 16;" :: "r"(d), "l"(s));
}
__device__ __forceinline__ void cp_commit() {
    asm volatile("cp.async.commit_group;");
}
template<int N> __device__ __forceinline__ void cp_wait() {
    asm volatile("cp.async.wait_group %0;" :: "n"(N));
}
__device__ __forceinline__ void ldm_x4(uint32_t& r0, uint32_t& r1, uint32_t& r2,
                                       uint32_t& r3, uint32_t addr) {
    asm volatile("ldmatrix.sync.aligned.m8n8.x4.shared.b16 {%0,%1,%2,%3}, [%4];"
                 : "=r"(r0), "=r"(r1), "=r"(r2), "=r"(r3) : "r"(addr));
}
__device__ __forceinline__ void ldm_x4t(uint32_t& r0, uint32_t& r1, uint32_t& r2,
                                        uint32_t& r3, uint32_t addr) {
    asm volatile("ldmatrix.sync.aligned.m8n8.x4.trans.shared.b16 {%0,%1,%2,%3}, [%4];"
                 : "=r"(r0), "=r"(r1), "=r"(r2), "=r"(r3) : "r"(addr));
}
__device__ __forceinline__ void mma16816(float* c, const uint32_t* a, const uint32_t* b) {
    asm volatile(
        "mma.sync.aligned.m16n8k16.row.col.f32.bf16.bf16.f32 "
        "{%0,%1,%2,%3}, {%4,%5,%6,%7}, {%8,%9}, {%0,%1,%2,%3};"
        : "+f"(c[0]), "+f"(c[1]), "+f"(c[2]), "+f"(c[3])
        : "r"(a[0]), "r"(a[1]), "r"(a[2]), "r"(a[3]), "r"(b[0]), "r"(b[1]));
}

// ---------------- K0: weight transpose + bf16 cast ---------------------------
__global__ void __launch_bounds__(256) transpose_w(const float* __restrict__ pin,
                                                   const float* __restrict__ pout) {
    int i = blockIdx.x * 256 + threadIdx.x;
    if (i < 3 * 256 * 64) {               // pinTb [dt][n][c]
        int c = i & 63;
        int n = (i >> 6) & 255;
        int dt = i >> 14;
        g_pinTb[i] = __float2bfloat16(pin[(n * 64 + c) * 3 + dt]);
    }
    if (i < 3 * 64 * 128) {               // poutTb [dt][n][k]
        int k = i & 127;
        int n = (i >> 7) & 63;
        int dt = i >> 13;
        g_poutTb[i] = __float2bfloat16(pout[(n * 128 + k) * 3 + dt]);
    }
}

// ---------------- K1: LayerNorm over channel dim per pixel -------------------
__global__ void __launch_bounds__(256) ln_kernel(const float* __restrict__ x,
                                                 const float* __restrict__ lw,
                                                 const float* __restrict__ lb) {
    int p = blockIdx.x * 256 + threadIdx.x;
    int bt = blockIdx.y;
    const float* xp = x + (size_t)bt * C_ * P + p;
    float v[64];
    float sum = 0.f;
#pragma unroll
    for (int c = 0; c < 64; c++) { v[c] = xp[(size_t)c * P]; sum += v[c]; }
    float mu = sum * (1.f / 64.f);
    float var = 0.f;
#pragma unroll
    for (int c = 0; c < 64; c++) { float d = v[c] - mu; var += d * d; }
    float rs = rsqrtf(var * (1.f / 64.f) + 1e-5f);
    bf16 ob[64];
#pragma unroll
    for (int c = 0; c < 64; c++)
        ob[c] = __float2bfloat16((v[c] - mu) * rs * lw[c] + lb[c]);
    uint4* dst = (uint4*)(g_xnb + ((size_t)bt * P + p) * 64);
#pragma unroll
    for (int i = 0; i < 8; i++) dst[i] = ((uint4*)ob)[i];
}

// ---------------- K2: pin conv3d GEMM, tensor cores, cp.async pipeline -------
// BM=128, BN=128. K chunked BK=32, double-buffered As/Bs.
__global__ void __launch_bounds__(256) pin_mma() {
    const int bt = blockIdx.z;
    const int t = bt & 7;
    const int p0 = blockIdx.x * 128;
    const int n0 = blockIdx.y * 128;
    __shared__ __align__(16) unsigned char shraw[40960];
    bf16* As = (bf16*)shraw;                  // [2][128][40]
    bf16* Bs = (bf16*)(shraw + 20480);        // [2][128][40]
    const int tid = threadIdx.x;
    const int wid = tid >> 5, l = tid & 31;
    const int wm = (wid & 3) * 32;
    const int wn = (wid >> 2) * 64;
    float acc[2][8][4];
#pragma unroll
    for (int i = 0; i < 2; i++)
#pragma unroll
        for (int j = 0; j < 8; j++)
#pragma unroll
            for (int k = 0; k < 4; k++) acc[i][j][k] = 0.f;

    const int dlo = (t == 0) ? 1 : 0;
    const int dhi = (t == 7) ? 1 : 2;
    const int nch = (dhi - dlo + 1) * 2;       // chunks of BK=32

    const int cr = tid >> 2, co = (tid & 3) * 8;   // copy: 4 thr/row, 2 rows/thr

    auto copy_chunk = [&](int i, int buf) {
        const int dt = dlo + (i >> 1);
        const int c0 = (i & 1) * 32;
        const bf16* ab = g_xnb + ((size_t)(bt + dt - 1) * P + p0) * 64 + c0;
        const bf16* wb = g_pinTb + ((size_t)dt * 256 + n0) * 64 + c0;
        bf16* ad = As + buf * 5120;
        bf16* bd = Bs + buf * 5120;
#pragma unroll
        for (int j = 0; j < 2; j++) {
            int r = cr + j * 64;
            cp16(smem_u32(ad + r * 40 + co), ab + (size_t)r * 64 + co);
            cp16(smem_u32(bd + r * 40 + co), wb + r * 64 + co);
        }
    };

    copy_chunk(0, 0);
    cp_commit();
#pragma unroll 1
    for (int i = 0; i < nch; i++) {
        if (i + 1 < nch) { copy_chunk(i + 1, (i + 1) & 1); cp_commit(); cp_wait<1>(); }
        else             { cp_wait<0>(); }
        __syncthreads();
        const bf16* Ab = As + (i & 1) * 5120;
        const bf16* Bb = Bs + (i & 1) * 5120;
#pragma unroll
        for (int kk = 0; kk < 2; kk++) {
            const int k0 = kk * 16;
            uint32_t a[2][4];
#pragma unroll
            for (int mt = 0; mt < 2; mt++)
                ldm_x4(a[mt][0], a[mt][1], a[mt][2], a[mt][3],
                       smem_u32(&Ab[(wm + mt * 16 + (l & 15)) * 40 + k0 + (l >> 4) * 8]));
            uint32_t b[8][2];
#pragma unroll
            for (int nt2 = 0; nt2 < 4; nt2++) {
                uint32_t r0, r1, r2, r3;
                ldm_x4(r0, r1, r2, r3,
                       smem_u32(&Bb[(wn + nt2 * 16 + (l & 15)) * 40 + k0 + (l >> 4) * 8]));
                b[nt2 * 2][0] = r0; b[nt2 * 2][1] = r2;
                b[nt2 * 2 + 1][0] = r1; b[nt2 * 2 + 1][1] = r3;
            }
#pragma unroll
            for (int mt = 0; mt < 2; mt++)
#pragma unroll
                for (int nt = 0; nt < 8; nt++) mma16816(acc[mt][nt], a[mt], b[nt]);
        }
        __syncthreads();
    }
    // epilogue: stage bf16 [128 ch][136 p] in smem (overlays As/Bs), coalesced stores
    bf16* st = (bf16*)shraw;
#pragma unroll
    for (int mt = 0; mt < 2; mt++)
#pragma unroll
        for (int nt = 0; nt < 8; nt++)
#pragma unroll
            for (int j = 0; j < 4; j++) {
                int p = wm + mt * 16 + (l >> 2) + ((j >= 2) ? 8 : 0);
                int ch = wn + nt * 8 + (l & 3) * 2 + (j & 1);
                st[ch * 136 + p] = __float2bfloat16(acc[mt][nt][j]);
            }
    __syncthreads();
    bf16* base = ((n0 == 0) ? g_x1 : g_x2) + (size_t)bt * 128 * P;
#pragma unroll
    for (int ps = 0; ps < 8; ps++) {
        int n = (tid >> 4) + ps * 16;
        int p = (tid & 15) * 8;
        *(uint4*)&base[(size_t)n * P + p0 + p] = *(uint4*)&st[n * 136 + p];
    }
}

// ---------------- K3: fused pooling branch — register-window dwconv ----------
__global__ void __launch_bounds__(256) pool_branch(const float* __restrict__ b1w,
                                                   const float* __restrict__ b1b,
                                                   const float* __restrict__ b2w,
                                                   const float* __restrict__ b2b) {
    __shared__ float sA[66 * 66];
    __shared__ float sB[66 * 66];
    __shared__ float red[8];
    const int btc = blockIdx.x;
    const int ch = btc & 127;
    const int tid = threadIdx.x;
    const bf16* src = g_x1 + (size_t)btc * P;

    for (int i = tid; i < 66; i += 256) {
        sA[i] = 0.f; sA[65 * 66 + i] = 0.f; sA[i * 66] = 0.f; sA[i * 66 + 65] = 0.f;
        sB[i] = 0.f; sB[65 * 66 + i] = 0.f; sB[i * 66] = 0.f; sB[i * 66 + 65] = 0.f;
    }
    for (int i = tid; i < 4096; i += 256) {
        int y = i >> 6, x = i & 63;
        __nv_bfloat162 a = ((const __nv_bfloat162*)(src + (y * 2) * 128))[x];
        __nv_bfloat162 b = ((const __nv_bfloat162*)(src + (y * 2 + 1) * 128))[x];
        sA[(y + 1) * 66 + x + 1] = 0.25f * (__bfloat162float(a.x) + __bfloat162float(a.y) +
                                            __bfloat162float(b.x) + __bfloat162float(b.y));
    }
    __syncthreads();

    const int x1c = tid & 63;
    const int y1s = (tid >> 6) * 16;
    for (int it = 0; it < 3; it++) {
        float w[9];
#pragma unroll
        for (int k = 0; k < 9; k++) w[k] = b1w[(it * 128 + ch) * 9 + k];
        const float bias = b1b[it * 128 + ch];
        const float* in = (it & 1) ? sB : sA;
        float* out = (it & 1) ? sA : sB;
        const float* col = in + x1c;
        float a0 = col[y1s * 66],       a1 = col[y1s * 66 + 1],       a2 = col[y1s * 66 + 2];
        float b0 = col[(y1s + 1) * 66], b1 = col[(y1s + 1) * 66 + 1], b2 = col[(y1s + 1) * 66 + 2];
#pragma unroll
        for (int yy = 0; yy < 16; yy++) {
            const int y = y1s + yy;
            const float c0 = col[(y + 2) * 66];
            const float c1 = col[(y + 2) * 66 + 1];
            const float c2 = col[(y + 2) * 66 + 2];
            out[(y + 1) * 66 + x1c + 1] = bias
                + a0 * w[0] + a1 * w[1] + a2 * w[2]
                + b0 * w[3] + b1 * w[4] + b2 * w[5]
                + c0 * w[6] + c1 * w[7] + c2 * w[8];
            a0 = b0; a1 = b1; a2 = b2;
            b0 = c0; b1 = c1; b2 = c2;
        }
        __syncthreads();
    }
    for (int i = tid; i < 34; i += 256) {
        sA[i] = 0.f; sA[33 * 34 + i] = 0.f; sA[i * 34] = 0.f; sA[i * 34 + 33] = 0.f;
    }
    for (int i = tid; i < 1024; i += 256) {
        int py = i >> 5, px = i & 31;
        const float* b0 = sB + (2 * py + 1) * 66 + 2 * px + 1;
        float m = fmaxf(fmaxf(b0[0], b0[1]), fmaxf(b0[66], b0[67]));
        sA[(py + 1) * 34 + px + 1] = m;
    }
    __syncthreads();

    const int x2c = tid & 31;
    const int y2s = (tid >> 5) * 4;
    for (int it = 0; it < 3; it++) {
        if (it == 0) {
            for (int i = tid; i < 34; i += 256) {
                sB[i] = 0.f; sB[33 * 34 + i] = 0.f; sB[i * 34] = 0.f; sB[i * 34 + 33] = 0.f;
            }
        }
        float w[9];
#pragma unroll
        for (int k = 0; k < 9; k++) w[k] = b2w[(it * 128 + ch) * 9 + k];
        const float bias = b2b[it * 128 + ch];
        const float* in = (it & 1) ? sB : sA;
        float* out = (it & 1) ? sA : sB;
        const float* col = in + x2c;
        float a0 = col[y2s * 34],       a1 = col[y2s * 34 + 1],       a2 = col[y2s * 34 + 2];
        float b0 = col[(y2s + 1) * 34], b1 = col[(y2s + 1) * 34 + 1], b2 = col[(y2s + 1) * 34 + 2];
#pragma unroll
        for (int yy = 0; yy < 4; yy++) {
            const int y = y2s + yy;
            const float c0 = col[(y + 2) * 34];
            const float c1 = col[(y + 2) * 34 + 1];
            const float c2 = col[(y + 2) * 34 + 2];
            out[(y + 1) * 34 + x2c + 1] = bias
                + a0 * w[0] + a1 * w[1] + a2 * w[2]
                + b0 * w[3] + b1 * w[4] + b2 * w[5]
                + c0 * w[6] + c1 * w[7] + c2 * w[8];
            a0 = b0; a1 = b1; a2 = b2;
            b0 = c0; b1 = c1; b2 = c2;
        }
        __syncthreads();
    }
    float s = 0.f;
    for (int i = tid; i < 1024; i += 256)
        s += sB[((i >> 5) + 1) * 34 + (i & 31) + 1];
#pragma unroll
    for (int o = 16; o; o >>= 1) s += __shfl_xor_sync(0xFFFFFFFFu, s, o);
    if ((tid & 31) == 0) red[tid >> 5] = s;
    __syncthreads();
    if (tid == 0) {
        float tot = 0.f;
#pragma unroll
        for (int i = 0; i < 8; i++) tot += red[i];
        g_pooled[btc] = tot * (1.f / 1024.f);
    }
}

// ---------------- K4: kern = pooled @ tok_w.T + tok_b ------------------------
__global__ void __launch_bounds__(128) kern_gemm(const float* __restrict__ tw,
                                                 const float* __restrict__ tb) {
    __shared__ float sp[2048];
    int tid = threadIdx.x;
    for (int i = tid; i < 2048; i += 128) sp[i] = g_pooled[i];
    __syncthreads();
    int j = blockIdx.x * 128 + tid;
    float acc[16];
#pragma unroll
    for (int b = 0; b < 16; b++) acc[b] = 0.f;
    const float4* wr = (const float4*)(tw + j * 128);
    for (int c4 = 0; c4 < 32; c4++) {
        float4 w = wr[c4];
#pragma unroll
        for (int b = 0; b < 16; b++) {
            const float* pp = sp + b * 128 + c4 * 4;
            acc[b] += w.x * pp[0] + w.y * pp[1] + w.z * pp[2] + w.w * pp[3];
        }
    }
    float bias = tb[j];
#pragma unroll
    for (int b = 0; b < 16; b++) g_kern[b * 1152 + j] = acc[b] + bias;
}

// ---------------- K5: dynamic depthwise conv + gate (vectorized) -------------
__global__ void __launch_bounds__(256) dyn_dw(const float* __restrict__ dwb) {
    __shared__ float s[66 * 130];
    const int btc = blockIdx.x;
    const int half = blockIdx.y;
    const int bt = btc >> 7, ch = btc & 127;
    const int r0 = half * 64;
    const int tid = threadIdx.x;
    const bf16* src = g_x1 + (size_t)btc * P;
    for (int r = tid; r < 66; r += 256) { s[r * 130] = 0.f; s[r * 130 + 129] = 0.f; }
    for (int i = tid; i < 1056; i += 256) {
        int row = i >> 4, xc = (i & 15) * 8;
        int rr = row + r0 - 1;
        float v[8];
        if (rr >= 0 && rr < 128) {
            uint4 u = *(const uint4*)(src + rr * 128 + xc);
            const bf16* pb = (const bf16*)&u;
#pragma unroll
            for (int k = 0; k < 8; k++) v[k] = __bfloat162float(pb[k]);
        } else {
#pragma unroll
            for (int k = 0; k < 8; k++) v[k] = 0.f;
        }
#pragma unroll
        for (int k = 0; k < 8; k++) s[row * 130 + xc + 1 + k] = v[k];
    }
    float kw[9];
#pragma unroll
    for (int k = 0; k < 9; k++) kw[k] = g_kern[bt * 1152 + ch * 9 + k];
    const float bias = dwb[ch];
    __syncthreads();
    const bf16* x2p = g_x2 + (size_t)btc * P + r0 * 128;
    bf16* dst = g_gated + (size_t)btc * P + r0 * 128;
    for (int i = tid; i < 4096; i += 256) {
        int y = i >> 6;
        int xp = (i & 63) * 2;
        const float* r = s + y * 130 + xp;
        float2 a0 = *(const float2*)(r);
        float2 a1 = *(const float2*)(r + 2);
        float2 b0 = *(const float2*)(r + 130);
        float2 b1 = *(const float2*)(r + 132);
        float2 c0 = *(const float2*)(r + 260);
        float2 c1 = *(const float2*)(r + 262);
        float o0 = a0.x * kw[0] + a0.y * kw[1] + a1.x * kw[2]
                 + b0.x * kw[3] + b0.y * kw[4] + b1.x * kw[5]
                 + c0.x * kw[6] + c0.y * kw[7] + c1.x * kw[8] + bias;
        float o1 = a0.y * kw[0] + a1.x * kw[1] + a1.y * kw[2]
                 + b0.y * kw[3] + b1.x * kw[4] + b1.y * kw[5]
                 + c0.y * kw[6] + c1.x * kw[7] + c1.y * kw[8] + bias;
        __nv_bfloat162 g2 = ((const __nv_bfloat162*)(x2p + y * 128))[xp >> 1];
        ((__nv_bfloat162*)(dst + y * 128))[xp >> 1] =
            __floats2bfloat162_rn(o0 * __bfloat162float(g2.x),
                                  o1 * __bfloat162float(g2.y));
    }
}

// ---------------- K6: pout conv3d GEMM + residual, cp.async pipeline ---------
// BM=128, BN=64. K = (taps x 128ch) chunked BK=32, double-buffered.
__global__ void __launch_bounds__(256) pout_mma(float* __restrict__ out,
                                                const float* __restrict__ x) {
    const int bt = blockIdx.y;
    const int t = bt & 7;
    const int p0 = blockIdx.x * 128;
    __shared__ __align__(16) unsigned char shraw[33792];
    bf16* As = (bf16*)shraw;                    // [2][32][136]  17408 B
    bf16* Bs = (bf16*)(shraw + 17408);          // [2][64][40]   10240 B
    float* st = (float*)shraw;                  // epilogue [64 ch][132 p]
    const int tid = threadIdx.x;
    const int wid = tid >> 5, l = tid & 31;
    const int wm = (wid & 3) * 32;
    const int wn = (wid >> 2) * 32;
    float acc[2][4][4];
#pragma unroll
    for (int i = 0; i < 2; i++)
#pragma unroll
        for (int j = 0; j < 4; j++)
#pragma unroll
            for (int k = 0; k < 4; k++) acc[i][j][k] = 0.f;

    const int dlo = (t == 0) ? 1 : 0;
    const int dhi = (t == 7) ? 1 : 2;
    const int nch = (dhi - dlo + 1) * 4;       // chunks of 32 ch

    const int arr = tid >> 4, aro = (tid & 15) * 8;  // A copy: 16 thr/row, 2 rows/thr
    const int brr = tid >> 2, bro = (tid & 3) * 8;   // B copy: 4 thr/row, 1 row/thr

    auto copy_chunk = [&](int i, int buf) {
        const int dt = dlo + (i >> 2);
        const int c0 = (i & 3) * 32;
        const bf16* ab = g_gated + ((size_t)((bt + dt - 1) * 128 + c0)) * P + p0;
        const bf16* wb = g_poutTb + ((size_t)dt * 64) * 128 + c0;
        bf16* ad = As + buf * 4352;
        bf16* bd = Bs + buf * 2560;
#pragma unroll
        for (int j = 0; j < 2; j++) {
            int r = arr + j * 16;
            cp16(smem_u32(ad + r * 136 + aro), ab + (size_t)r * P + aro);
        }
        cp16(smem_u32(bd + brr * 40 + bro), wb + brr * 128 + bro);
    };

    copy_chunk(0, 0);
    cp_commit();
#pragma unroll 1
    for (int i = 0; i < nch; i++) {
        if (i + 1 < nch) { copy_chunk(i + 1, (i + 1) & 1); cp_commit(); cp_wait<1>(); }
        else             { cp_wait<0>(); }
        __syncthreads();
        const bf16* Ab = As + (i & 1) * 4352;
        const bf16* Bb = Bs + (i & 1) * 2560;
#pragma unroll
        for (int kk = 0; kk < 2; kk++) {
            const int k0 = kk * 16;
            uint32_t a[2][4];
#pragma unroll
            for (int mt = 0; mt < 2; mt++) {
                int row = k0 + (l & 7) + ((l >> 4) << 3);
                int col = wm + mt * 16 + ((l >> 3) & 1) * 8;
                ldm_x4t(a[mt][0], a[mt][1], a[mt][2], a[mt][3],
                        smem_u32(&Ab[row * 136 + col]));
            }
            uint32_t b[4][2];
#pragma unroll
            for (int nt2 = 0; nt2 < 2; nt2++) {
                uint32_t r0, r1, r2, r3;
                ldm_x4(r0, r1, r2, r3,
                       smem_u32(&Bb[(wn + nt2 * 16 + (l & 15)) * 40 + k0 + (l >> 4) * 8]));
                b[nt2 * 2][0] = r0; b[nt2 * 2][1] = r2;
                b[nt2 * 2 + 1][0] = r1; b[nt2 * 2 + 1][1] = r3;
            }
#pragma unroll
            for (int mt = 0; mt < 2; mt++)
#pragma unroll
                for (int nt = 0; nt < 4; nt++) mma16816(acc[mt][nt], a[mt], b[nt]);
        }
        __syncthreads();
    }
    // epilogue: stage fp32 [64 ch][132 p] (overlays As/Bs), residual-add + store
#pragma unroll
    for (int mt = 0; mt < 2; mt++)
#pragma unroll
        for (int nt = 0; nt < 4; nt++)
#pragma unroll
            for (int j = 0; j < 4; j++) {
                int p = wm + mt * 16 + (l >> 2) + ((j >= 2) ? 8 : 0);
                int ch = wn + nt * 8 + (l & 3) * 2 + (j & 1);
                st[ch * 132 + p] = acc[mt][nt][j];
            }
    __syncthreads();
    const size_t base = (size_t)bt * 64 * P + p0;
#pragma unroll
    for (int ps = 0; ps < 8; ps++) {
        int ch = (tid >> 5) + ps * 8;
        int p = (tid & 31) * 4;
        float4 v = *(float4*)&st[ch * 132 + p];
        float4 xr = *(const float4*)&x[base + (size_t)ch * P + p];
        v.x += xr.x; v.y += xr.y; v.z += xr.z; v.w += xr.w;
        *(float4*)&out[base + (size_t)ch * P + p] = v;
    }
}

// ---------------- launch ------------------------------------------------------
extern "C" void kernel_launch(void* const* d_in, const int* in_sizes, int n_in,
                              void* d_out, int out_size) {
    (void)in_sizes; (void)n_in; (void)out_size;
    const float* x      = (const float*)d_in[0];
    const float* ln_w   = (const float*)d_in[1];
    const float* ln_b   = (const float*)d_in[2];
    const float* pin_w  = (const float*)d_in[3];
    const float* pout_w = (const float*)d_in[4];
    const float* b1_w   = (const float*)d_in[5];
    const float* b1_b   = (const float*)d_in[6];
    const float* b2_w   = (const float*)d_in[7];
    const float* b2_b   = (const float*)d_in[8];
    const float* tok_w  = (const float*)d_in[9];
    const float* tok_b  = (const float*)d_in[10];
    const float* dw_bias= (const float*)d_in[11];
    float* out = (float*)d_out;

    transpose_w<<<192, 256>>>(pin_w, pout_w);
    ln_kernel<<<dim3(P / 256, BT), 256>>>(x, ln_w, ln_b);
    pin_mma<<<dim3(P / 128, 2, BT), 256>>>();
    pool_branch<<<BT * HID, 256>>>(b1_w, b1_b, b2_w, b2_b);
    kern_gemm<<<9, 128>>>(tok_w, tok_b);
    dyn_dw<<<dim3(BT * HID, 2), 256>>>(dw_bias);
    pout_mma<<<dim3(P / 128, BT), 256>>>(out, x);
}

// round 7
// speedup vs baseline: 1.0389x; 1.0389x over previous
#include <cuda_runtime.h>
#include <cuda_bf16.h>
#include <cstdint>

// Problem constants
#define BT 16          // b*t
#define C_ 64          // dim
#define HID 128
#define P 16384        // H*W = 128*128
typedef __nv_bfloat16 bf16;

// ---------------- scratch (device globals; no runtime allocation) ------------
__device__ bf16  g_xnb[(size_t)BT * P * C_];     // layernormed x, bf16 [bt][p][c]
__device__ bf16  g_x1[(size_t)BT * HID * P];     // pin out ch 0..127, bf16 [bt][ch][p]
__device__ bf16  g_x2[(size_t)BT * HID * P];     // pin out ch 128..255
__device__ bf16  g_gated[(size_t)BT * HID * P];  // (dyn dwconv + bias) * x2, [bt][ch][p]
__device__ float g_pooled[BT * HID];
__device__ float g_kern[BT * HID * 9];
__device__ bf16  g_pinTb[3 * 256 * 64];          // [dt][n(256)][c(64)]
__device__ bf16  g_poutTb[3 * 64 * 128];         // [dt][n(64)][k(128)]

// ---------------- mma helpers -------------------------------------------------
__device__ __forceinline__ uint32_t smem_u32(const void* p) {
    return (uint32_t)__cvta_generic_to_shared(p);
}
__device__ __forceinline__ void ldm_x4(uint32_t& r0, uint32_t& r1, uint32_t& r2,
                                       uint32_t& r3, uint32_t addr) {
    asm volatile("ldmatrix.sync.aligned.m8n8.x4.shared.b16 {%0,%1,%2,%3}, [%4];"
                 : "=r"(r0), "=r"(r1), "=r"(r2), "=r"(r3) : "r"(addr));
}
__device__ __forceinline__ void ldm_x4t(uint32_t& r0, uint32_t& r1, uint32_t& r2,
                                        uint32_t& r3, uint32_t addr) {
    asm volatile("ldmatrix.sync.aligned.m8n8.x4.trans.shared.b16 {%0,%1,%2,%3}, [%4];"
                 : "=r"(r0), "=r"(r1), "=r"(r2), "=r"(r3) : "r"(addr));
}
__device__ __forceinline__ void mma16816(float* c, const uint32_t* a, const uint32_t* b) {
    asm volatile(
        "mma.sync.aligned.m16n8k16.row.col.f32.bf16.bf16.f32 "
        "{%0,%1,%2,%3}, {%4,%5,%6,%7}, {%8,%9}, {%0,%1,%2,%3};"
        : "+f"(c[0]), "+f"(c[1]), "+f"(c[2]), "+f"(c[3])
        : "r"(a[0]), "r"(a[1]), "r"(a[2]), "r"(a[3]), "r"(b[0]), "r"(b[1]));
}

// ---------------- K0: weight transpose + bf16 cast ---------------------------
__global__ void __launch_bounds__(256) transpose_w(const float* __restrict__ pin,
                                                   const float* __restrict__ pout) {
    int i = blockIdx.x * 256 + threadIdx.x;
    if (i < 3 * 256 * 64) {               // pinTb [dt][n][c]
        int c = i & 63;
        int n = (i >> 6) & 255;
        int dt = i >> 14;
        g_pinTb[i] = __float2bfloat16(pin[(n * 64 + c) * 3 + dt]);
    }
    if (i < 3 * 64 * 128) {               // poutTb [dt][n][k]
        int k = i & 127;
        int n = (i >> 7) & 63;
        int dt = i >> 13;
        g_poutTb[i] = __float2bfloat16(pout[(n * 128 + k) * 3 + dt]);
    }
}

// ---------------- K1: LayerNorm over channel dim per pixel -------------------
__global__ void __launch_bounds__(256) ln_kernel(const float* __restrict__ x,
                                                 const float* __restrict__ lw,
                                                 const float* __restrict__ lb) {
    int p = blockIdx.x * 256 + threadIdx.x;
    int bt = blockIdx.y;
    const float* xp = x + (size_t)bt * C_ * P + p;
    float v[64];
    float sum = 0.f;
#pragma unroll
    for (int c = 0; c < 64; c++) { v[c] = xp[(size_t)c * P]; sum += v[c]; }
    float mu = sum * (1.f / 64.f);
    float var = 0.f;
#pragma unroll
    for (int c = 0; c < 64; c++) { float d = v[c] - mu; var += d * d; }
    float rs = rsqrtf(var * (1.f / 64.f) + 1e-5f);
    bf16 ob[64];
#pragma unroll
    for (int c = 0; c < 64; c++)
        ob[c] = __float2bfloat16((v[c] - mu) * rs * lw[c] + lb[c]);
    uint4* dst = (uint4*)(g_xnb + ((size_t)bt * P + p) * 64);
#pragma unroll
    for (int i = 0; i < 8; i++) dst[i] = ((uint4*)ob)[i];
}

// ---------------- K2: pin conv3d GEMM, tensor cores (R4 version) -------------
__global__ void __launch_bounds__(256) pin_mma() {
    const int bt = blockIdx.z;
    const int t = bt & 7;
    const int p0 = blockIdx.x * 128;
    const int n0 = blockIdx.y * 128;
    __shared__ __align__(16) bf16 sh[2 * 128 * 72];      // As | Bs (36864 B)
    bf16* As = sh;                 // [128 p][72]
    bf16* Bs = sh + 128 * 72;      // [128 n][72]
    const int tid = threadIdx.x;
    const int wid = tid >> 5, l = tid & 31;
    const int wm = (wid & 3) * 32;
    const int wn = (wid >> 2) * 64;
    float acc[2][8][4];
#pragma unroll
    for (int i = 0; i < 2; i++)
#pragma unroll
        for (int j = 0; j < 8; j++)
#pragma unroll
            for (int k = 0; k < 4; k++) acc[i][j][k] = 0.f;

    const int lr = tid >> 3, lc = (tid & 7) * 8;
#pragma unroll 1
    for (int dt = 0; dt < 3; dt++) {
        const int ts = t + dt - 1;
        if (ts < 0 || ts > 7) continue;
        const bf16* ab = g_xnb + ((size_t)(bt + dt - 1) * P + p0) * 64;
        const bf16* wb = g_pinTb + (dt * 256 + n0) * 64;
#pragma unroll
        for (int ps = 0; ps < 4; ps++) {
            *(uint4*)&As[(lr + ps * 32) * 72 + lc] = *(const uint4*)&ab[(size_t)(lr + ps * 32) * 64 + lc];
            *(uint4*)&Bs[(lr + ps * 32) * 72 + lc] = *(const uint4*)&wb[(lr + ps * 32) * 64 + lc];
        }
        __syncthreads();
#pragma unroll
        for (int kk = 0; kk < 4; kk++) {
            const int k0 = kk * 16;
            uint32_t a[2][4];
#pragma unroll
            for (int mt = 0; mt < 2; mt++)
                ldm_x4(a[mt][0], a[mt][1], a[mt][2], a[mt][3],
                       smem_u32(&As[(wm + mt * 16 + (l & 15)) * 72 + k0 + (l >> 4) * 8]));
            uint32_t b[8][2];
#pragma unroll
            for (int nt2 = 0; nt2 < 4; nt2++) {
                uint32_t r0, r1, r2, r3;
                ldm_x4(r0, r1, r2, r3,
                       smem_u32(&Bs[(wn + nt2 * 16 + (l & 15)) * 72 + k0 + (l >> 4) * 8]));
                b[nt2 * 2][0] = r0; b[nt2 * 2][1] = r2;
                b[nt2 * 2 + 1][0] = r1; b[nt2 * 2 + 1][1] = r3;
            }
#pragma unroll
            for (int mt = 0; mt < 2; mt++)
#pragma unroll
                for (int nt = 0; nt < 8; nt++) mma16816(acc[mt][nt], a[mt], b[nt]);
        }
        __syncthreads();
    }
    bf16* st = sh;
#pragma unroll
    for (int mt = 0; mt < 2; mt++)
#pragma unroll
        for (int nt = 0; nt < 8; nt++)
#pragma unroll
            for (int j = 0; j < 4; j++) {
                int p = wm + mt * 16 + (l >> 2) + ((j >= 2) ? 8 : 0);
                int ch = wn + nt * 8 + (l & 3) * 2 + (j & 1);
                st[ch * 136 + p] = __float2bfloat16(acc[mt][nt][j]);
            }
    __syncthreads();
    bf16* base = ((n0 == 0) ? g_x1 : g_x2) + (size_t)bt * 128 * P;
#pragma unroll
    for (int ps = 0; ps < 8; ps++) {
        int n = (tid >> 4) + ps * 16;
        int p = (tid & 15) * 8;
        *(uint4*)&base[(size_t)n * P + p0 + p] = *(uint4*)&st[n * 136 + p];
    }
}

// ---------------- K3: pooling branch — 4-wide ILP dwconv ---------------------
// stage1: padded 66x66, stage2: padded 34x34. Each thread computes 4 x-adjacent
// outputs per row with a 3x6 register window sliding down rows:
// 6 LDS + 36 FMA per 4 pixels.
__global__ void __launch_bounds__(256) pool_branch(const float* __restrict__ b1w,
                                                   const float* __restrict__ b1b,
                                                   const float* __restrict__ b2w,
                                                   const float* __restrict__ b2b) {
    __shared__ float sA[66 * 66];
    __shared__ float sB[66 * 66];
    __shared__ float red[8];
    const int btc = blockIdx.x;
    const int ch = btc & 127;
    const int tid = threadIdx.x;
    const bf16* src = g_x1 + (size_t)btc * P;

    // zero halos of both 66-stride buffers
    for (int i = tid; i < 66; i += 256) {
        sA[i] = 0.f; sA[65 * 66 + i] = 0.f; sA[i * 66] = 0.f; sA[i * 66 + 65] = 0.f;
        sB[i] = 0.f; sB[65 * 66 + i] = 0.f; sB[i * 66] = 0.f; sB[i * 66 + 65] = 0.f;
    }
    // avgpool 128x128 -> 64x64, 4 outputs per thread per iter (uint4 loads)
#pragma unroll
    for (int it = 0; it < 4; it++) {
        int g = (it * 256 + tid) * 4;     // first of 4 consecutive outputs
        int y = g >> 6, x = g & 63;
        uint4 u0 = *(const uint4*)(src + (y * 2) * 128 + x * 2);
        uint4 u1 = *(const uint4*)(src + (y * 2 + 1) * 128 + x * 2);
        const __nv_bfloat162* p0 = (const __nv_bfloat162*)&u0;
        const __nv_bfloat162* p1 = (const __nv_bfloat162*)&u1;
        float* d = sA + (y + 1) * 66 + x + 1;
#pragma unroll
        for (int j = 0; j < 4; j++)
            d[j] = 0.25f * (__bfloat162float(p0[j].x) + __bfloat162float(p0[j].y) +
                            __bfloat162float(p1[j].x) + __bfloat162float(p1[j].y));
    }
    __syncthreads();

    // stage 1: 3x dwconv 3x3 @64x64
    {
        const int c0 = (tid & 15) * 4;    // col group: output cols c0..c0+3
        const int y0 = (tid >> 4) * 4;    // row strip: output rows y0..y0+3
        for (int it = 0; it < 3; it++) {
            float w[9];
#pragma unroll
            for (int k = 0; k < 9; k++) w[k] = b1w[(it * 128 + ch) * 9 + k];
            const float bias = b1b[it * 128 + ch];
            const float* in = (it & 1) ? sB : sA;
            float* out = (it & 1) ? sA : sB;
            float win[3][6];
#pragma unroll
            for (int k = 0; k < 6; k++) {
                win[0][k] = in[y0 * 66 + c0 + k];          // buf row y0   (= out row y0 - 1)
                win[1][k] = in[(y0 + 1) * 66 + c0 + k];    // buf row y0+1 (= out row y0)
            }
#pragma unroll
            for (int yy = 0; yy < 4; yy++) {
                float* nw = win[(yy + 2) % 3];
#pragma unroll
                for (int k = 0; k < 6; k++) nw[k] = in[(y0 + 2 + yy) * 66 + c0 + k];
                const float* rA = win[yy % 3];
                const float* rB = win[(yy + 1) % 3];
                const float* rC = win[(yy + 2) % 3];
                float* d = out + (y0 + yy + 1) * 66 + c0 + 1;
#pragma unroll
                for (int j = 0; j < 4; j++)
                    d[j] = bias
                        + rA[j] * w[0] + rA[j + 1] * w[1] + rA[j + 2] * w[2]
                        + rB[j] * w[3] + rB[j + 1] * w[4] + rB[j + 2] * w[5]
                        + rC[j] * w[6] + rC[j + 1] * w[7] + rC[j + 2] * w[8];
            }
            __syncthreads();
        }
    }
    // result in sB66; maxpool 64->32 into sA34 (sA66 dead) + zero sA34 halos
    for (int i = tid; i < 34; i += 256) {
        sA[i] = 0.f; sA[33 * 34 + i] = 0.f; sA[i * 34] = 0.f; sA[i * 34 + 33] = 0.f;
    }
    {
        int py = tid >> 3;                 // 0..31
        int px0 = (tid & 7) * 4;           // 4 outputs
        const float* b0 = sB + (2 * py + 1) * 66 + 2 * px0 + 1;
        const float* b1 = b0 + 66;
        float* d = sA + (py + 1) * 34 + px0 + 1;
#pragma unroll
        for (int j = 0; j < 4; j++)
            d[j] = fmaxf(fmaxf(b0[2 * j], b0[2 * j + 1]),
                         fmaxf(b1[2 * j], b1[2 * j + 1]));
    }
    __syncthreads();

    // stage 2: 3x dwconv 3x3 @32x32 (1 row x 4 cols per thread)
    {
        const int c0 = (tid & 7) * 4;
        const int y = tid >> 3;            // 0..31
        for (int it = 0; it < 3; it++) {
            if (it == 0) {
                for (int i = tid; i < 34; i += 256) {
                    sB[i] = 0.f; sB[33 * 34 + i] = 0.f; sB[i * 34] = 0.f; sB[i * 34 + 33] = 0.f;
                }
            }
            float w[9];
#pragma unroll
            for (int k = 0; k < 9; k++) w[k] = b2w[(it * 128 + ch) * 9 + k];
            const float bias = b2b[it * 128 + ch];
            const float* in = (it & 1) ? sB : sA;
            float* out = (it & 1) ? sA : sB;
            float rA[6], rB[6], rC[6];
#pragma unroll
            for (int k = 0; k < 6; k++) {
                rA[k] = in[y * 34 + c0 + k];
                rB[k] = in[(y + 1) * 34 + c0 + k];
                rC[k] = in[(y + 2) * 34 + c0 + k];
            }
            float* d = out + (y + 1) * 34 + c0 + 1;
#pragma unroll
            for (int j = 0; j < 4; j++)
                d[j] = bias
                    + rA[j] * w[0] + rA[j + 1] * w[1] + rA[j + 2] * w[2]
                    + rB[j] * w[3] + rB[j + 1] * w[4] + rB[j + 2] * w[5]
                    + rC[j] * w[6] + rC[j + 1] * w[7] + rC[j + 2] * w[8];
            __syncthreads();
        }
    }
    // final in sB34 interior; spatial mean (4 consecutive cols per thread)
    float s = 0.f;
    {
        int y = tid >> 3, x0 = (tid & 7) * 4;
        const float* r = sB + (y + 1) * 34 + x0 + 1;
#pragma unroll
        for (int j = 0; j < 4; j++) s += r[j];
    }
#pragma unroll
    for (int o = 16; o; o >>= 1) s += __shfl_xor_sync(0xFFFFFFFFu, s, o);
    if ((tid & 31) == 0) red[tid >> 5] = s;
    __syncthreads();
    if (tid == 0) {
        float tot = 0.f;
#pragma unroll
        for (int i = 0; i < 8; i++) tot += red[i];
        g_pooled[btc] = tot * (1.f / 1024.f);
    }
}

// ---------------- K4: kern = pooled @ tok_w.T + tok_b ------------------------
__global__ void __launch_bounds__(128) kern_gemm(const float* __restrict__ tw,
                                                 const float* __restrict__ tb) {
    __shared__ float sp[2048];
    int tid = threadIdx.x;
    for (int i = tid; i < 2048; i += 128) sp[i] = g_pooled[i];
    __syncthreads();
    int j = blockIdx.x * 128 + tid;
    float acc[16];
#pragma unroll
    for (int b = 0; b < 16; b++) acc[b] = 0.f;
    const float4* wr = (const float4*)(tw + j * 128);
    for (int c4 = 0; c4 < 32; c4++) {
        float4 w = wr[c4];
#pragma unroll
        for (int b = 0; b < 16; b++) {
            const float* pp = sp + b * 128 + c4 * 4;
            acc[b] += w.x * pp[0] + w.y * pp[1] + w.z * pp[2] + w.w * pp[3];
        }
    }
    float bias = tb[j];
#pragma unroll
    for (int b = 0; b < 16; b++) g_kern[b * 1152 + j] = acc[b] + bias;
}

// ---------------- K5: dynamic depthwise conv + gate (vectorized) -------------
__global__ void __launch_bounds__(256) dyn_dw(const float* __restrict__ dwb) {
    __shared__ float s[66 * 130];
    const int btc = blockIdx.x;
    const int half = blockIdx.y;
    const int bt = btc >> 7, ch = btc & 127;
    const int r0 = half * 64;
    const int tid = threadIdx.x;
    const bf16* src = g_x1 + (size_t)btc * P;
    for (int r = tid; r < 66; r += 256) { s[r * 130] = 0.f; s[r * 130 + 129] = 0.f; }
    for (int i = tid; i < 1056; i += 256) {
        int row = i >> 4, xc = (i & 15) * 8;
        int rr = row + r0 - 1;
        float v[8];
        if (rr >= 0 && rr < 128) {
            uint4 u = *(const uint4*)(src + rr * 128 + xc);
            const bf16* pb = (const bf16*)&u;
#pragma unroll
            for (int k = 0; k < 8; k++) v[k] = __bfloat162float(pb[k]);
        } else {
#pragma unroll
            for (int k = 0; k < 8; k++) v[k] = 0.f;
        }
#pragma unroll
        for (int k = 0; k < 8; k++) s[row * 130 + xc + 1 + k] = v[k];
    }
    float kw[9];
#pragma unroll
    for (int k = 0; k < 9; k++) kw[k] = g_kern[bt * 1152 + ch * 9 + k];
    const float bias = dwb[ch];
    __syncthreads();
    const bf16* x2p = g_x2 + (size_t)btc * P + r0 * 128;
    bf16* dst = g_gated + (size_t)btc * P + r0 * 128;
    for (int i = tid; i < 4096; i += 256) {
        int y = i >> 6;
        int xp = (i & 63) * 2;
        const float* r = s + y * 130 + xp;
        float2 a0 = *(const float2*)(r);
        float2 a1 = *(const float2*)(r + 2);
        float2 b0 = *(const float2*)(r + 130);
        float2 b1 = *(const float2*)(r + 132);
        float2 c0 = *(const float2*)(r + 260);
        float2 c1 = *(const float2*)(r + 262);
        float o0 = a0.x * kw[0] + a0.y * kw[1] + a1.x * kw[2]
                 + b0.x * kw[3] + b0.y * kw[4] + b1.x * kw[5]
                 + c0.x * kw[6] + c0.y * kw[7] + c1.x * kw[8] + bias;
        float o1 = a0.y * kw[0] + a1.x * kw[1] + a1.y * kw[2]
                 + b0.y * kw[3] + b1.x * kw[4] + b1.y * kw[5]
                 + c0.y * kw[6] + c1.x * kw[7] + c1.y * kw[8] + bias;
        __nv_bfloat162 g2 = ((const __nv_bfloat162*)(x2p + y * 128))[xp >> 1];
        ((__nv_bfloat162*)(dst + y * 128))[xp >> 1] =
            __floats2bfloat162_rn(o0 * __bfloat162float(g2.x),
                                  o1 * __bfloat162float(g2.y));
    }
}

// ---------------- K6: pout conv3d GEMM + residual (R4 version) ---------------
__global__ void __launch_bounds__(256) pout_mma(float* __restrict__ out,
                                                const float* __restrict__ x) {
    const int bt = blockIdx.y;
    const int t = bt & 7;
    const int p0 = blockIdx.x * 128;
    __shared__ __align__(16) unsigned char shraw[34816];
    bf16* As = (bf16*)shraw;                    // [64 ch][136 p]
    bf16* Bs = (bf16*)(shraw + 17408);          // [64 n][72]
    float* st = (float*)shraw;                  // [64 ch][132 p] (epilogue)
    const int tid = threadIdx.x;
    const int wid = tid >> 5, l = tid & 31;
    const int wm = (wid & 3) * 32;
    const int wn = (wid >> 2) * 32;
    float acc[2][4][4];
#pragma unroll
    for (int i = 0; i < 2; i++)
#pragma unroll
        for (int j = 0; j < 4; j++)
#pragma unroll
            for (int k = 0; k < 4; k++) acc[i][j][k] = 0.f;

    const int ar = tid >> 4, ac = (tid & 15) * 8;
    const int br = tid >> 3, bc = (tid & 7) * 8;
#pragma unroll 1
    for (int dt = 0; dt < 3; dt++) {
        const int ts = t + dt - 1;
        if (ts < 0 || ts > 7) continue;
#pragma unroll 1
        for (int half = 0; half < 2; half++) {
            const int ch0 = half * 64;
            const bf16* ab = g_gated + ((size_t)((bt + dt - 1) * 128 + ch0)) * P + p0;
            const bf16* wb = g_poutTb + (dt * 64) * 128 + ch0;
#pragma unroll
            for (int ps = 0; ps < 4; ps++)
                *(uint4*)&As[(ar + ps * 16) * 136 + ac] =
                    *(const uint4*)&ab[(size_t)(ar + ps * 16) * P + ac];
#pragma unroll
            for (int ps = 0; ps < 2; ps++)
                *(uint4*)&Bs[(br + ps * 32) * 72 + bc] =
                    *(const uint4*)&wb[(br + ps * 32) * 128 + bc];
            __syncthreads();
#pragma unroll
            for (int kk = 0; kk < 4; kk++) {
                const int k0 = kk * 16;
                uint32_t a[2][4];
#pragma unroll
                for (int mt = 0; mt < 2; mt++) {
                    int row = k0 + (l & 7) + ((l >> 4) << 3);
                    int col = wm + mt * 16 + ((l >> 3) & 1) * 8;
                    ldm_x4t(a[mt][0], a[mt][1], a[mt][2], a[mt][3],
                            smem_u32(&As[row * 136 + col]));
                }
                uint32_t b[4][2];
#pragma unroll
                for (int nt2 = 0; nt2 < 2; nt2++) {
                    uint32_t r0, r1, r2, r3;
                    ldm_x4(r0, r1, r2, r3,
                           smem_u32(&Bs[(wn + nt2 * 16 + (l & 15)) * 72 + k0 + (l >> 4) * 8]));
                    b[nt2 * 2][0] = r0; b[nt2 * 2][1] = r2;
                    b[nt2 * 2 + 1][0] = r1; b[nt2 * 2 + 1][1] = r3;
                }
#pragma unroll
                for (int mt = 0; mt < 2; mt++)
#pragma unroll
                    for (int nt = 0; nt < 4; nt++) mma16816(acc[mt][nt], a[mt], b[nt]);
            }
            __syncthreads();
        }
    }
#pragma unroll
    for (int mt = 0; mt < 2; mt++)
#pragma unroll
        for (int nt = 0; nt < 4; nt++)
#pragma unroll
            for (int j = 0; j < 4; j++) {
                int p = wm + mt * 16 + (l >> 2) + ((j >= 2) ? 8 : 0);
                int ch = wn + nt * 8 + (l & 3) * 2 + (j & 1);
                st[ch * 132 + p] = acc[mt][nt][j];
            }
    __syncthreads();
    const size_t base = (size_t)bt * 64 * P + p0;
#pragma unroll
    for (int ps = 0; ps < 8; ps++) {
        int ch = (tid >> 5) + ps * 8;
        int p = (tid & 31) * 4;
        float4 v = *(float4*)&st[ch * 132 + p];
        float4 xr = *(const float4*)&x[base + (size_t)ch * P + p];
        v.x += xr.x; v.y += xr.y; v.z += xr.z; v.w += xr.w;
        *(float4*)&out[base + (size_t)ch * P + p] = v;
    }
}

// ---------------- launch ------------------------------------------------------
extern "C" void kernel_launch(void* const* d_in, const int* in_sizes, int n_in,
                              void* d_out, int out_size) {
    (void)in_sizes; (void)n_in; (void)out_size;
    const float* x      = (const float*)d_in[0];
    const float* ln_w   = (const float*)d_in[1];
    const float* ln_b   = (const float*)d_in[2];
    const float* pin_w  = (const float*)d_in[3];
    const float* pout_w = (const float*)d_in[4];
    const float* b1_w   = (const float*)d_in[5];
    const float* b1_b   = (const float*)d_in[6];
    const float* b2_w   = (const float*)d_in[7];
    const float* b2_b   = (const float*)d_in[8];
    const float* tok_w  = (const float*)d_in[9];
    const float* tok_b  = (const float*)d_in[10];
    const float* dw_bias= (const float*)d_in[11];
    float* out = (float*)d_out;

    transpose_w<<<192, 256>>>(pin_w, pout_w);
    ln_kernel<<<dim3(P / 256, BT), 256>>>(x, ln_w, ln_b);
    pin_mma<<<dim3(P / 128, 2, BT), 256>>>();
    pool_branch<<<BT * HID, 256>>>(b1_w, b1_b, b2_w, b2_b);
    kern_gemm<<<9, 128>>>(tok_w, tok_b);
    dyn_dw<<<dim3(BT * HID, 2), 256>>>(dw_bias);
    pout_mma<<<dim3(P / 128, BT), 256>>>(out, x);
}

// round 9
// speedup vs baseline: 1.0445x; 1.0054x over previous
#include <cuda_runtime.h>
#include <cuda_bf16.h>
#include <cstdint>

// Problem constants
#define BT 16          // b*t
#define C_ 64          // dim
#define HID 128
#define P 16384        // H*W = 128*128
typedef __nv_bfloat16 bf16;

// ---------------- scratch (device globals; no runtime allocation) ------------
__device__ bf16  g_xnb[(size_t)BT * P * C_];     // layernormed x, bf16 [bt][p][c]
__device__ bf16  g_x1[(size_t)BT * HID * P];     // pin out ch 0..127, bf16 [bt][ch][p]
__device__ bf16  g_x2[(size_t)BT * HID * P];     // pin out ch 128..255
__device__ bf16  g_gated[(size_t)BT * HID * P];  // (dyn dwconv + bias) * x2, [bt][ch][p]
__device__ float g_pooled[BT * HID];
__device__ float g_kern[BT * HID * 9];
__device__ bf16  g_pinTb[3 * 256 * 64];          // [dt][n(256)][c(64)]
__device__ bf16  g_poutTb[3 * 64 * 128];         // [dt][n(64)][k(128)]

// ---------------- mma helpers -------------------------------------------------
__device__ __forceinline__ uint32_t smem_u32(const void* p) {
    return (uint32_t)__cvta_generic_to_shared(p);
}
__device__ __forceinline__ void ldm_x4(uint32_t& r0, uint32_t& r1, uint32_t& r2,
                                       uint32_t& r3, uint32_t addr) {
    asm volatile("ldmatrix.sync.aligned.m8n8.x4.shared.b16 {%0,%1,%2,%3}, [%4];"
                 : "=r"(r0), "=r"(r1), "=r"(r2), "=r"(r3) : "r"(addr));
}
__device__ __forceinline__ void ldm_x4t(uint32_t& r0, uint32_t& r1, uint32_t& r2,
                                        uint32_t& r3, uint32_t addr) {
    asm volatile("ldmatrix.sync.aligned.m8n8.x4.trans.shared.b16 {%0,%1,%2,%3}, [%4];"
                 : "=r"(r0), "=r"(r1), "=r"(r2), "=r"(r3) : "r"(addr));
}
__device__ __forceinline__ void mma16816(float* c, const uint32_t* a, const uint32_t* b) {
    asm volatile(
        "mma.sync.aligned.m16n8k16.row.col.f32.bf16.bf16.f32 "
        "{%0,%1,%2,%3}, {%4,%5,%6,%7}, {%8,%9}, {%0,%1,%2,%3};"
        : "+f"(c[0]), "+f"(c[1]), "+f"(c[2]), "+f"(c[3])
        : "r"(a[0]), "r"(a[1]), "r"(a[2]), "r"(a[3]), "r"(b[0]), "r"(b[1]));
}

// 6-wide row (float4+float2) contribution to 4 adjacent conv outputs.
// Order matches scalar version: acc[j] += r[j]*w0 + r[j+1]*w1 + r[j+2]*w2.
__device__ __forceinline__ void row6(const float4 a, const float2 b,
                                     float w0, float w1, float w2, float* acc) {
    acc[0] += a.x * w0 + a.y * w1 + a.z * w2;
    acc[1] += a.y * w0 + a.z * w1 + a.w * w2;
    acc[2] += a.z * w0 + a.w * w1 + b.x * w2;
    acc[3] += a.w * w0 + b.x * w1 + b.y * w2;
}

// ---------------- K0: weight transpose + bf16 cast ---------------------------
__global__ void __launch_bounds__(256) transpose_w(const float* __restrict__ pin,
                                                   const float* __restrict__ pout) {
    int i = blockIdx.x * 256 + threadIdx.x;
    if (i < 3 * 256 * 64) {               // pinTb [dt][n][c]
        int c = i & 63;
        int n = (i >> 6) & 255;
        int dt = i >> 14;
        g_pinTb[i] = __float2bfloat16(pin[(n * 64 + c) * 3 + dt]);
    }
    if (i < 3 * 64 * 128) {               // poutTb [dt][n][k]
        int k = i & 127;
        int n = (i >> 7) & 63;
        int dt = i >> 13;
        g_poutTb[i] = __float2bfloat16(pout[(n * 128 + k) * 3 + dt]);
    }
}

// ---------------- K1: LayerNorm over channel dim per pixel -------------------
__global__ void __launch_bounds__(256) ln_kernel(const float* __restrict__ x,
                                                 const float* __restrict__ lw,
                                                 const float* __restrict__ lb) {
    int p = blockIdx.x * 256 + threadIdx.x;
    int bt = blockIdx.y;
    const float* xp = x + (size_t)bt * C_ * P + p;
    float v[64];
    float sum = 0.f;
#pragma unroll
    for (int c = 0; c < 64; c++) { v[c] = xp[(size_t)c * P]; sum += v[c]; }
    float mu = sum * (1.f / 64.f);
    float var = 0.f;
#pragma unroll
    for (int c = 0; c < 64; c++) { float d = v[c] - mu; var += d * d; }
    float rs = rsqrtf(var * (1.f / 64.f) + 1e-5f);
    bf16 ob[64];
#pragma unroll
    for (int c = 0; c < 64; c++)
        ob[c] = __float2bfloat16((v[c] - mu) * rs * lw[c] + lb[c]);
    uint4* dst = (uint4*)(g_xnb + ((size_t)bt * P + p) * 64);
#pragma unroll
    for (int i = 0; i < 8; i++) dst[i] = ((uint4*)ob)[i];
}

// ---------------- K2: pin conv3d GEMM, tensor cores --------------------------
__global__ void __launch_bounds__(256) pin_mma() {
    const int bt = blockIdx.z;
    const int t = bt & 7;
    const int p0 = blockIdx.x * 128;
    const int n0 = blockIdx.y * 128;
    __shared__ __align__(16) bf16 sh[2 * 128 * 72];      // As | Bs (36864 B)
    bf16* As = sh;                 // [128 p][72]
    bf16* Bs = sh + 128 * 72;      // [128 n][72]
    const int tid = threadIdx.x;
    const int wid = tid >> 5, l = tid & 31;
    const int wm = (wid & 3) * 32;
    const int wn = (wid >> 2) * 64;
    float acc[2][8][4];
#pragma unroll
    for (int i = 0; i < 2; i++)
#pragma unroll
        for (int j = 0; j < 8; j++)
#pragma unroll
            for (int k = 0; k < 4; k++) acc[i][j][k] = 0.f;

    const int lr = tid >> 3, lc = (tid & 7) * 8;
#pragma unroll 1
    for (int dt = 0; dt < 3; dt++) {
        const int ts = t + dt - 1;
        if (ts < 0 || ts > 7) continue;
        const bf16* ab = g_xnb + ((size_t)(bt + dt - 1) * P + p0) * 64;
        const bf16* wb = g_pinTb + (dt * 256 + n0) * 64;
#pragma unroll
        for (int ps = 0; ps < 4; ps++) {
            *(uint4*)&As[(lr + ps * 32) * 72 + lc] = *(const uint4*)&ab[(size_t)(lr + ps * 32) * 64 + lc];
            *(uint4*)&Bs[(lr + ps * 32) * 72 + lc] = *(const uint4*)&wb[(lr + ps * 32) * 64 + lc];
        }
        __syncthreads();
#pragma unroll
        for (int kk = 0; kk < 4; kk++) {
            const int k0 = kk * 16;
            uint32_t a[2][4];
#pragma unroll
            for (int mt = 0; mt < 2; mt++)
                ldm_x4(a[mt][0], a[mt][1], a[mt][2], a[mt][3],
                       smem_u32(&As[(wm + mt * 16 + (l & 15)) * 72 + k0 + (l >> 4) * 8]));
            uint32_t b[8][2];
#pragma unroll
            for (int nt2 = 0; nt2 < 4; nt2++) {
                uint32_t r0, r1, r2, r3;
                ldm_x4(r0, r1, r2, r3,
                       smem_u32(&Bs[(wn + nt2 * 16 + (l & 15)) * 72 + k0 + (l >> 4) * 8]));
                b[nt2 * 2][0] = r0; b[nt2 * 2][1] = r2;
                b[nt2 * 2 + 1][0] = r1; b[nt2 * 2 + 1][1] = r3;
            }
#pragma unroll
            for (int mt = 0; mt < 2; mt++)
#pragma unroll
                for (int nt = 0; nt < 8; nt++) mma16816(acc[mt][nt], a[mt], b[nt]);
        }
        __syncthreads();
    }
    bf16* st = sh;
#pragma unroll
    for (int mt = 0; mt < 2; mt++)
#pragma unroll
        for (int nt = 0; nt < 8; nt++)
#pragma unroll
            for (int j = 0; j < 4; j++) {
                int p = wm + mt * 16 + (l >> 2) + ((j >= 2) ? 8 : 0);
                int ch = wn + nt * 8 + (l & 3) * 2 + (j & 1);
                st[ch * 136 + p] = __float2bfloat16(acc[mt][nt][j]);
            }
    __syncthreads();
    bf16* base = ((n0 == 0) ? g_x1 : g_x2) + (size_t)bt * 128 * P;
#pragma unroll
    for (int ps = 0; ps < 8; ps++) {
        int n = (tid >> 4) + ps * 16;
        int p = (tid & 15) * 8;
        *(uint4*)&base[(size_t)n * P + p0 + p] = *(uint4*)&st[n * 136 + p];
    }
}

// ---------------- K3: pooling branch — 4-wide ILP + vector LDS ---------------
// stage1: 66 rows x stride 68 (16B-aligned rows), stage2: 34 rows x stride 36.
// Window loads are float4+float2 (6 smem phases per 4 px vs 24 scalar).
#define S1 68
#define S2 36
__global__ void __launch_bounds__(256) pool_branch(const float* __restrict__ b1w,
                                                   const float* __restrict__ b1b,
                                                   const float* __restrict__ b2w,
                                                   const float* __restrict__ b2b) {
    __shared__ __align__(16) float sA[66 * S1];
    __shared__ __align__(16) float sB[66 * S1];
    __shared__ float red[8];
    const int btc = blockIdx.x;
    const int ch = btc & 127;
    const int tid = threadIdx.x;
    const bf16* src = g_x1 + (size_t)btc * P;

    // zero halos (rows 0/65, cols 0/65) of both stage-1 buffers
    for (int i = tid; i < 66; i += 256) {
        sA[i] = 0.f; sA[65 * S1 + i] = 0.f; sA[i * S1] = 0.f; sA[i * S1 + 65] = 0.f;
        sB[i] = 0.f; sB[65 * S1 + i] = 0.f; sB[i * S1] = 0.f; sB[i * S1 + 65] = 0.f;
    }
    // avgpool 128x128 -> 64x64, 4 outputs per thread per iter (uint4 loads)
#pragma unroll
    for (int it = 0; it < 4; it++) {
        int g = (it * 256 + tid) * 4;
        int y = g >> 6, x = g & 63;
        uint4 u0 = *(const uint4*)(src + (y * 2) * 128 + x * 2);
        uint4 u1 = *(const uint4*)(src + (y * 2 + 1) * 128 + x * 2);
        const __nv_bfloat162* p0 = (const __nv_bfloat162*)&u0;
        const __nv_bfloat162* p1 = (const __nv_bfloat162*)&u1;
        float* d = sA + (y + 1) * S1 + x + 1;
#pragma unroll
        for (int j = 0; j < 4; j++)
            d[j] = 0.25f * (__bfloat162float(p0[j].x) + __bfloat162float(p0[j].y) +
                            __bfloat162float(p1[j].x) + __bfloat162float(p1[j].y));
    }
    __syncthreads();

    // stage 1: 3x dwconv 3x3 @64x64, vectorized 3x6 window sliding down 4 rows
    {
        const int c0 = (tid & 15) * 4;    // output cols c0+1..c0+4 (buffer coords)
        const int y0 = (tid >> 4) * 4;    // output rows y0+1..y0+4
        for (int it = 0; it < 3; it++) {
            float w[9];
#pragma unroll
            for (int k = 0; k < 9; k++) w[k] = b1w[(it * 128 + ch) * 9 + k];
            const float bias = b1b[it * 128 + ch];
            const float* in = (it & 1) ? sB : sA;
            float* out = (it & 1) ? sA : sB;
            float4 wa[3]; float2 wb2[3];
            wa[0] = *(const float4*)&in[y0 * S1 + c0];
            wb2[0] = *(const float2*)&in[y0 * S1 + c0 + 4];
            wa[1] = *(const float4*)&in[(y0 + 1) * S1 + c0];
            wb2[1] = *(const float2*)&in[(y0 + 1) * S1 + c0 + 4];
#pragma unroll
            for (int yy = 0; yy < 4; yy++) {
                const int nslot = (yy + 2) % 3;
                wa[nslot] = *(const float4*)&in[(y0 + 2 + yy) * S1 + c0];
                wb2[nslot] = *(const float2*)&in[(y0 + 2 + yy) * S1 + c0 + 4];
                float acc[4] = {bias, bias, bias, bias};
                row6(wa[yy % 3],       wb2[yy % 3],       w[0], w[1], w[2], acc);
                row6(wa[(yy + 1) % 3], wb2[(yy + 1) % 3], w[3], w[4], w[5], acc);
                row6(wa[nslot],        wb2[nslot],        w[6], w[7], w[8], acc);
                float* d = out + (y0 + yy + 1) * S1 + c0 + 1;
#pragma unroll
                for (int j = 0; j < 4; j++) d[j] = acc[j];
            }
            __syncthreads();
        }
    }
    // result in sB(S1); maxpool 64->32 into sA(S2) + zero sA(S2) halos
    for (int i = tid; i < 34; i += 256) {
        sA[i] = 0.f; sA[33 * S2 + i] = 0.f; sA[i * S2] = 0.f; sA[i * S2 + 33] = 0.f;
    }
    {
        int py = tid >> 3;                 // 0..31
        int px0 = (tid & 7) * 4;           // 4 outputs
        // need stage-1 interior cols 2*px0+1 .. 2*px0+8 -> load aligned 10-wide
        const float* r0 = sB + (2 * py + 1) * S1 + 2 * px0;
        const float* r1 = r0 + S1;
        float4 a0 = *(const float4*)r0;        float4 a1 = *(const float4*)(r0 + 4);
        float2 a2 = *(const float2*)(r0 + 8);
        float4 b0 = *(const float4*)r1;        float4 b1 = *(const float4*)(r1 + 4);
        float2 b2 = *(const float2*)(r1 + 8);
        float* d = sA + (py + 1) * S2 + px0 + 1;
        d[0] = fmaxf(fmaxf(a0.y, a0.z), fmaxf(b0.y, b0.z));
        d[1] = fmaxf(fmaxf(a0.w, a1.x), fmaxf(b0.w, b1.x));
        d[2] = fmaxf(fmaxf(a1.y, a1.z), fmaxf(b1.y, b1.z));
        d[3] = fmaxf(fmaxf(a1.w, a2.x), fmaxf(b1.w, b2.x));
    }
    __syncthreads();

    // stage 2: 3x dwconv 3x3 @32x32 (1 row x 4 cols per thread), vector loads
    {
        const int c0 = (tid & 7) * 4;
        const int y = tid >> 3;            // 0..31
        for (int it = 0; it < 3; it++) {
            if (it == 0) {
                for (int i = tid; i < 34; i += 256) {
                    sB[i] = 0.f; sB[33 * S2 + i] = 0.f; sB[i * S2] = 0.f; sB[i * S2 + 33] = 0.f;
                }
            }
            float w[9];
#pragma unroll
            for (int k = 0; k < 9; k++) w[k] = b2w[(it * 128 + ch) * 9 + k];
            const float bias = b2b[it * 128 + ch];
            const float* in = (it & 1) ? sB : sA;
            float* out = (it & 1) ? sA : sB;
            float acc[4] = {bias, bias, bias, bias};
#pragma unroll
            for (int rr = 0; rr < 3; rr++) {
                float4 va = *(const float4*)&in[(y + rr) * S2 + c0];
                float2 vb = *(const float2*)&in[(y + rr) * S2 + c0 + 4];
                row6(va, vb, w[rr * 3], w[rr * 3 + 1], w[rr * 3 + 2], acc);
            }
            float* d = out + (y + 1) * S2 + c0 + 1;
#pragma unroll
            for (int j = 0; j < 4; j++) d[j] = acc[j];
            __syncthreads();
        }
    }
    // final in sB(S2) interior; spatial mean
    float s = 0.f;
    {
        int y = tid >> 3, x0 = (tid & 7) * 4;
        const float* r = sB + (y + 1) * S2 + x0 + 1;
#pragma unroll
        for (int j = 0; j < 4; j++) s += r[j];
    }
#pragma unroll
    for (int o = 16; o; o >>= 1) s += __shfl_xor_sync(0xFFFFFFFFu, s, o);
    if ((tid & 31) == 0) red[tid >> 5] = s;
    __syncthreads();
    if (tid == 0) {
        float tot = 0.f;
#pragma unroll
        for (int i = 0; i < 8; i++) tot += red[i];
        g_pooled[btc] = tot * (1.f / 1024.f);
    }
}

// ---------------- K4: kern = pooled @ tok_w.T + tok_b ------------------------
__global__ void __launch_bounds__(128) kern_gemm(const float* __restrict__ tw,
                                                 const float* __restrict__ tb) {
    __shared__ float sp[2048];
    int tid = threadIdx.x;
    for (int i = tid; i < 2048; i += 128) sp[i] = g_pooled[i];
    __syncthreads();
    int j = blockIdx.x * 128 + tid;
    float acc[16];
#pragma unroll
    for (int b = 0; b < 16; b++) acc[b] = 0.f;
    const float4* wr = (const float4*)(tw + j * 128);
    for (int c4 = 0; c4 < 32; c4++) {
        float4 w = wr[c4];
#pragma unroll
        for (int b = 0; b < 16; b++) {
            const float* pp = sp + b * 128 + c4 * 4;
            acc[b] += w.x * pp[0] + w.y * pp[1] + w.z * pp[2] + w.w * pp[3];
        }
    }
    float bias = tb[j];
#pragma unroll
    for (int b = 0; b < 16; b++) g_kern[b * 1152 + j] = acc[b] + bias;
}

// ---------------- K5: dynamic depthwise conv + gate (vectorized) -------------
__global__ void __launch_bounds__(256) dyn_dw(const float* __restrict__ dwb) {
    __shared__ float s[66 * 130];
    const int btc = blockIdx.x;
    const int half = blockIdx.y;
    const int bt = btc >> 7, ch = btc & 127;
    const int r0 = half * 64;
    const int tid = threadIdx.x;
    const bf16* src = g_x1 + (size_t)btc * P;
    for (int r = tid; r < 66; r += 256) { s[r * 130] = 0.f; s[r * 130 + 129] = 0.f; }
    for (int i = tid; i < 1056; i += 256) {
        int row = i >> 4, xc = (i & 15) * 8;
        int rr = row + r0 - 1;
        float v[8];
        if (rr >= 0 && rr < 128) {
            uint4 u = *(const uint4*)(src + rr * 128 + xc);
            const bf16* pb = (const bf16*)&u;
#pragma unroll
            for (int k = 0; k < 8; k++) v[k] = __bfloat162float(pb[k]);
        } else {
#pragma unroll
            for (int k = 0; k < 8; k++) v[k] = 0.f;
        }
#pragma unroll
        for (int k = 0; k < 8; k++) s[row * 130 + xc + 1 + k] = v[k];
    }
    float kw[9];
#pragma unroll
    for (int k = 0; k < 9; k++) kw[k] = g_kern[bt * 1152 + ch * 9 + k];
    const float bias = dwb[ch];
    __syncthreads();
    const bf16* x2p = g_x2 + (size_t)btc * P + r0 * 128;
    bf16* dst = g_gated + (size_t)btc * P + r0 * 128;
    for (int i = tid; i < 4096; i += 256) {
        int y = i >> 6;
        int xp = (i & 63) * 2;
        const float* r = s + y * 130 + xp;
        float2 a0 = *(const float2*)(r);
        float2 a1 = *(const float2*)(r + 2);
        float2 b0 = *(const float2*)(r + 130);
        float2 b1 = *(const float2*)(r + 132);
        float2 c0 = *(const float2*)(r + 260);
        float2 c1 = *(const float2*)(r + 262);
        float o0 = a0.x * kw[0] + a0.y * kw[1] + a1.x * kw[2]
                 + b0.x * kw[3] + b0.y * kw[4] + b1.x * kw[5]
                 + c0.x * kw[6] + c0.y * kw[7] + c1.x * kw[8] + bias;
        float o1 = a0.y * kw[0] + a1.x * kw[1] + a1.y * kw[2]
                 + b0.y * kw[3] + b1.x * kw[4] + b1.y * kw[5]
                 + c0.y * kw[6] + c1.x * kw[7] + c1.y * kw[8] + bias;
        __nv_bfloat162 g2 = ((const __nv_bfloat162*)(x2p + y * 128))[xp >> 1];
        ((__nv_bfloat162*)(dst + y * 128))[xp >> 1] =
            __floats2bfloat162_rn(o0 * __bfloat162float(g2.x),
                                  o1 * __bfloat162float(g2.y));
    }
}

// ---------------- K6: pout conv3d GEMM + residual, tensor cores --------------
__global__ void __launch_bounds__(256) pout_mma(float* __restrict__ out,
                                                const float* __restrict__ x) {
    const int bt = blockIdx.y;
    const int t = bt & 7;
    const int p0 = blockIdx.x * 128;
    __shared__ __align__(16) unsigned char shraw[34816];
    bf16* As = (bf16*)shraw;                    // [64 ch][136 p]
    bf16* Bs = (bf16*)(shraw + 17408);          // [64 n][72]
    float* st = (float*)shraw;                  // [64 ch][132 p] (epilogue)
    const int tid = threadIdx.x;
    const int wid = tid >> 5, l = tid & 31;
    const int wm = (wid & 3) * 32;
    const int wn = (wid >> 2) * 32;
    float acc[2][4][4];
#pragma unroll
    for (int i = 0; i < 2; i++)
#pragma unroll
        for (int j = 0; j < 4; j++)
#pragma unroll
            for (int k = 0; k < 4; k++) acc[i][j][k] = 0.f;

    const int ar = tid >> 4, ac = (tid & 15) * 8;
    const int br = tid >> 3, bc = (tid & 7) * 8;
#pragma unroll 1
    for (int dt = 0; dt < 3; dt++) {
        const int ts = t + dt - 1;
        if (ts < 0 || ts > 7) continue;
#pragma unroll 1
        for (int half = 0; half < 2; half++) {
            const int ch0 = half * 64;
            const bf16* ab = g_gated + ((size_t)((bt + dt - 1) * 128 + ch0)) * P + p0;
            const bf16* wb = g_poutTb + (dt * 64) * 128 + ch0;
#pragma unroll
            for (int ps = 0; ps < 4; ps++)
                *(uint4*)&As[(ar + ps * 16) * 136 + ac] =
                    *(const uint4*)&ab[(size_t)(ar + ps * 16) * P + ac];
#pragma unroll
            for (int ps = 0; ps < 2; ps++)
                *(uint4*)&Bs[(br + ps * 32) * 72 + bc] =
                    *(const uint4*)&wb[(br + ps * 32) * 128 + bc];
            __syncthreads();
#pragma unroll
            for (int kk = 0; kk < 4; kk++) {
                const int k0 = kk * 16;
                uint32_t a[2][4];
#pragma unroll
                for (int mt = 0; mt < 2; mt++) {
                    int row = k0 + (l & 7) + ((l >> 4) << 3);
                    int col = wm + mt * 16 + ((l >> 3) & 1) * 8;
                    ldm_x4t(a[mt][0], a[mt][1], a[mt][2], a[mt][3],
                            smem_u32(&As[row * 136 + col]));
                }
                uint32_t b[4][2];
#pragma unroll
                for (int nt2 = 0; nt2 < 2; nt2++) {
                    uint32_t r0, r1, r2, r3;
                    ldm_x4(r0, r1, r2, r3,
                           smem_u32(&Bs[(wn + nt2 * 16 + (l & 15)) * 72 + k0 + (l >> 4) * 8]));
                    b[nt2 * 2][0] = r0; b[nt2 * 2][1] = r2;
                    b[nt2 * 2 + 1][0] = r1; b[nt2 * 2 + 1][1] = r3;
                }
#pragma unroll
                for (int mt = 0; mt < 2; mt++)
#pragma unroll
                    for (int nt = 0; nt < 4; nt++) mma16816(acc[mt][nt], a[mt], b[nt]);
            }
            __syncthreads();
        }
    }
#pragma unroll
    for (int mt = 0; mt < 2; mt++)
#pragma unroll
        for (int nt = 0; nt < 4; nt++)
#pragma unroll
            for (int j = 0; j < 4; j++) {
                int p = wm + mt * 16 + (l >> 2) + ((j >= 2) ? 8 : 0);
                int ch = wn + nt * 8 + (l & 3) * 2 + (j & 1);
                st[ch * 132 + p] = acc[mt][nt][j];
            }
    __syncthreads();
    const size_t base = (size_t)bt * 64 * P + p0;
#pragma unroll
    for (int ps = 0; ps < 8; ps++) {
        int ch = (tid >> 5) + ps * 8;
        int p = (tid & 31) * 4;
        float4 v = *(float4*)&st[ch * 132 + p];
        float4 xr = *(const float4*)&x[base + (size_t)ch * P + p];
        v.x += xr.x; v.y += xr.y; v.z += xr.z; v.w += xr.w;
        *(float4*)&out[base + (size_t)ch * P + p] = v;
    }
}

// ---------------- launch ------------------------------------------------------
extern "C" void kernel_launch(void* const* d_in, const int* in_sizes, int n_in,
                              void* d_out, int out_size) {
    (void)in_sizes; (void)n_in; (void)out_size;
    const float* x      = (const float*)d_in[0];
    const float* ln_w   = (const float*)d_in[1];
    const float* ln_b   = (const float*)d_in[2];
    const float* pin_w  = (const float*)d_in[3];
    const float* pout_w = (const float*)d_in[4];
    const float* b1_w   = (const float*)d_in[5];
    const float* b1_b   = (const float*)d_in[6];
    const float* b2_w   = (const float*)d_in[7];
    const float* b2_b   = (const float*)d_in[8];
    const float* tok_w  = (const float*)d_in[9];
    const float* tok_b  = (const float*)d_in[10];
    const float* dw_bias= (const float*)d_in[11];
    float* out = (float*)d_out;

    transpose_w<<<192, 256>>>(pin_w, pout_w);
    ln_kernel<<<dim3(P / 256, BT), 256>>>(x, ln_w, ln_b);
    pin_mma<<<dim3(P / 128, 2, BT), 256>>>();
    pool_branch<<<BT * HID, 256>>>(b1_w, b1_b, b2_w, b2_b);
    kern_gemm<<<9, 128>>>(tok_w, tok_b);
    dyn_dw<<<dim3(BT * HID, 2), 256>>>(dw_bias);
    pout_mma<<<dim3(P / 128, BT), 256>>>(out, x);
}